// round 1
// baseline (speedup 1.0000x reference)
#include <cuda_runtime.h>
#include <cuda_bf16.h>
#include <cstdint>

// LinearUnit single-step LRU cell:
//   out[b, j] = state[b, j] * a_diag[j] + (in[b,0]+in[b,1]) * b_col[j]
// a_diag = cat(as_real[:S], as_imag[:S]); b_col = cat(bs_real[:S], bs_imag[:S])
// BATCH=4096, NUM_UNITS=8192 (=2S), S=4096.
// Pure HBM-bound streamer: 128MB read + 128MB (or 256MB) write.

static constexpr int BATCH     = 4096;
static constexpr int NUM_UNITS = 8192;
static constexpr int S         = NUM_UNITS / 2;
static constexpr int NU4       = NUM_UNITS / 4;   // 2048 float4 per row
static constexpr int S4        = S / 4;           // 1024
static constexpr long long TOTAL4 = (long long)BATCH * NU4;  // 8,388,608

__global__ __launch_bounds__(256)
void lru_cell_kernel(const float* __restrict__ inputs,    // (B, 2)
                     const float* __restrict__ state,     // (B, NU)
                     const float* __restrict__ as_real,   // (NU,)
                     const float* __restrict__ as_imag,   // (NU,)
                     const float* __restrict__ bs_real,   // (NU,)
                     const float* __restrict__ bs_imag,   // (NU,)
                     float* __restrict__ out,
                     int duplicate)                        // 1 if out holds (y, y)
{
    const float4* state4   = reinterpret_cast<const float4*>(state);
    const float4* as_real4 = reinterpret_cast<const float4*>(as_real);
    const float4* as_imag4 = reinterpret_cast<const float4*>(as_imag);
    const float4* bs_real4 = reinterpret_cast<const float4*>(bs_real);
    const float4* bs_imag4 = reinterpret_cast<const float4*>(bs_imag);
    float4*       out4     = reinterpret_cast<float4*>(out);

    long long idx    = (long long)blockIdx.x * blockDim.x + threadIdx.x;
    long long stride = (long long)gridDim.x * blockDim.x;

    for (; idx < TOTAL4; idx += stride) {
        int b  = (int)(idx >> 11);        // idx / NU4  (NU4 = 2048)
        int j4 = (int)(idx & (NU4 - 1));  // idx % NU4

        // per-row input sum (L2-broadcast; tiny working set)
        float2 in2 = __ldg(reinterpret_cast<const float2*>(inputs) + b);
        float u = in2.x + in2.y;

        // diag params: first S entries come from *_real, next S from *_imag.
        // S4=1024 so a float4 never straddles the boundary.
        float4 a, c;
        if (j4 < S4) {
            a = __ldg(as_real4 + j4);
            c = __ldg(bs_real4 + j4);
        } else {
            a = __ldg(as_imag4 + (j4 - S4));
            c = __ldg(bs_imag4 + (j4 - S4));
        }

        float4 s = state4[idx];
        float4 r;
        r.x = fmaf(s.x, a.x, u * c.x);
        r.y = fmaf(s.y, a.y, u * c.y);
        r.z = fmaf(s.z, a.z, u * c.z);
        r.w = fmaf(s.w, a.w, u * c.w);

        out4[idx] = r;
        if (duplicate) {
            out4[idx + TOTAL4] = r;
        }
    }
}

extern "C" void kernel_launch(void* const* d_in, const int* in_sizes, int n_in,
                              void* d_out, int out_size) {
    const float* inputs  = (const float*)d_in[0];
    const float* state   = (const float*)d_in[1];
    const float* as_real = (const float*)d_in[2];
    const float* as_imag = (const float*)d_in[3];
    const float* bs_real = (const float*)d_in[4];
    const float* bs_imag = (const float*)d_in[5];
    float* out = (float*)d_out;

    long long total = (long long)BATCH * NUM_UNITS;
    int duplicate = ((long long)out_size >= 2 * total) ? 1 : 0;

    // One thread per float4; 8.4M threads. 256 thr/block.
    int threads = 256;
    long long blocks64 = (TOTAL4 + threads - 1) / threads;  // 32768
    int blocks = (int)blocks64;

    lru_cell_kernel<<<blocks, threads>>>(inputs, state, as_real, as_imag,
                                         bs_real, bs_imag, out, duplicate);
}

// round 5
// speedup vs baseline: 1.0654x; 1.0654x over previous
#include <cuda_runtime.h>
#include <cuda_bf16.h>
#include <cstdint>

// LinearUnit single-step LRU cell (elementwise, HBM-bound):
//   out[b, j] = state[b, j] * a_diag[j] + (in[b,0]+in[b,1]) * b_col[j]
// BATCH=4096, NUM_UNITS=8192 (=2S), S=4096.
// Traffic floor: 128MB state read + 128/256MB write.

static constexpr int BATCH     = 4096;
static constexpr int NUM_UNITS = 8192;
static constexpr int S         = NUM_UNITS / 2;
static constexpr int NU4       = NUM_UNITS / 4;   // 2048 float4 per row
static constexpr int S4        = S / 4;           // 1024
static constexpr int TOTAL4    = BATCH * NU4;     // 8,388,608 (fits int32)

// Tiling: 256 threads/block, 2 float4 per thread -> 512 float4 per block.
// 2048 float4 per row -> exactly 4 blocks per row, so b / u / real-imag
// selection are block-uniform (no divergence, hoistable to UR).
static constexpr int THREADS        = 256;
static constexpr int ITEMS          = 2;
static constexpr int F4_PER_BLOCK   = THREADS * ITEMS;        // 512
static constexpr int BLOCKS_PER_ROW = NU4 / F4_PER_BLOCK;     // 4
static constexpr int GRID           = BATCH * BLOCKS_PER_ROW; // 16384

template <int DUP>
__global__ __launch_bounds__(THREADS)
void lru_cell_kernel(const float* __restrict__ inputs,    // (B, 2)
                     const float* __restrict__ state,     // (B, NU)
                     const float* __restrict__ as_real,   // (NU,)
                     const float* __restrict__ as_imag,   // (NU,)
                     const float* __restrict__ bs_real,   // (NU,)
                     const float* __restrict__ bs_imag,   // (NU,)
                     float* __restrict__ out)
{
    const float4* state4   = reinterpret_cast<const float4*>(state);
    const float4* as_real4 = reinterpret_cast<const float4*>(as_real);
    const float4* as_imag4 = reinterpret_cast<const float4*>(as_imag);
    const float4* bs_real4 = reinterpret_cast<const float4*>(bs_real);
    const float4* bs_imag4 = reinterpret_cast<const float4*>(bs_imag);
    float4*       out4     = reinterpret_cast<float4*>(out);

    const int blk = blockIdx.x;
    const int b   = blk >> 2;                     // row (block-uniform)
    const int j4b = (blk & 3) * F4_PER_BLOCK;     // row-local float4 offset of block

    // Per-row input sum: one 8B load, L1/L2-resident, block-uniform value.
    const float2 in2 = __ldg(reinterpret_cast<const float2*>(inputs) + b);
    const float  u   = in2.x + in2.y;

    // Block sits entirely in the real half (j4b+511 < 1024) or the imag half
    // (boundary S4=1024 is a multiple of 512) -> uniform select, no divergence.
    const float4* ap;
    const float4* cp;
    if (j4b < S4) { ap = as_real4;       cp = bs_real4; }
    else          { ap = as_imag4 - S4;  cp = bs_imag4 - S4; }

    const int j4_0  = j4b + threadIdx.x;          // item 0
    const int base  = b * NU4;                    // row base in float4 units

    // Issue both state loads (streaming, evict-first) before consuming either.
    const int idx0 = base + j4_0;
    const int idx1 = idx0 + THREADS;
    float4 s0 = __ldcs(state4 + idx0);
    float4 s1 = __ldcs(state4 + idx1);

    // Params are hot in L1/L2 across the whole grid.
    float4 a0 = __ldg(ap + j4_0);
    float4 c0 = __ldg(cp + j4_0);
    float4 a1 = __ldg(ap + j4_0 + THREADS);
    float4 c1 = __ldg(cp + j4_0 + THREADS);

    float4 r0, r1;
    r0.x = fmaf(s0.x, a0.x, u * c0.x);
    r0.y = fmaf(s0.y, a0.y, u * c0.y);
    r0.z = fmaf(s0.z, a0.z, u * c0.z);
    r0.w = fmaf(s0.w, a0.w, u * c0.w);
    r1.x = fmaf(s1.x, a1.x, u * c1.x);
    r1.y = fmaf(s1.y, a1.y, u * c1.y);
    r1.z = fmaf(s1.z, a1.z, u * c1.z);
    r1.w = fmaf(s1.w, a1.w, u * c1.w);

    __stcs(out4 + idx0, r0);
    __stcs(out4 + idx1, r1);
    if (DUP) {
        __stcs(out4 + idx0 + TOTAL4, r0);
        __stcs(out4 + idx1 + TOTAL4, r1);
    }
}

extern "C" void kernel_launch(void* const* d_in, const int* in_sizes, int n_in,
                              void* d_out, int out_size) {
    const float* inputs  = (const float*)d_in[0];
    const float* state   = (const float*)d_in[1];
    const float* as_real = (const float*)d_in[2];
    const float* as_imag = (const float*)d_in[3];
    const float* bs_real = (const float*)d_in[4];
    const float* bs_imag = (const float*)d_in[5];
    float* out = (float*)d_out;

    const long long total = (long long)BATCH * NUM_UNITS;
    if ((long long)out_size >= 2 * total) {
        lru_cell_kernel<1><<<GRID, THREADS>>>(inputs, state, as_real, as_imag,
                                              bs_real, bs_imag, out);
    } else {
        lru_cell_kernel<0><<<GRID, THREADS>>>(inputs, state, as_real, as_imag,
                                              bs_real, bs_imag, out);
    }
}

// round 7
// speedup vs baseline: 1.0660x; 1.0005x over previous
#include <cuda_runtime.h>
#include <cuda_bf16.h>
#include <cstdint>

// LinearUnit single-step LRU cell (elementwise, HBM-bound):
//   out[b, j] = state[b, j] * a_diag[j] + (in[b,0]+in[b,1]) * b_col[j]
// BATCH=4096, NUM_UNITS=8192 (=2S), S=4096. Output = (y, y) duplicated.
// Traffic floor: 128MB state read + 256MB write = 384MB.

static constexpr int BATCH     = 4096;
static constexpr int NUM_UNITS = 8192;
static constexpr int S         = NUM_UNITS / 2;
static constexpr int NU4       = NUM_UNITS / 4;   // 2048 float4 per row
static constexpr int S4        = S / 4;           // 1024
static constexpr int TOTAL4    = BATCH * NU4;     // 8,388,608 (fits int32)

// 256 threads/block, 4 float4 per thread -> 1024 float4 per block.
// Each block covers exactly one half-row (real or imag): blk&1 selects the
// param half with zero divergence; row index is blk>>1. MLP_p1=4.
static constexpr int THREADS        = 256;
static constexpr int ITEMS          = 4;
static constexpr int F4_PER_BLOCK   = THREADS * ITEMS;        // 1024 == S4
static constexpr int BLOCKS_PER_ROW = NU4 / F4_PER_BLOCK;     // 2
static constexpr int GRID           = BATCH * BLOCKS_PER_ROW; // 8192

template <int DUP>
__global__ __launch_bounds__(THREADS)
void lru_cell_kernel(const float* __restrict__ inputs,    // (B, 2)
                     const float* __restrict__ state,     // (B, NU)
                     const float* __restrict__ as_real,   // (NU,)
                     const float* __restrict__ as_imag,   // (NU,)
                     const float* __restrict__ bs_real,   // (NU,)
                     const float* __restrict__ bs_imag,   // (NU,)
                     float* __restrict__ out)
{
    const float4* state4   = reinterpret_cast<const float4*>(state);
    float4*       out4     = reinterpret_cast<float4*>(out);

    const int blk  = blockIdx.x;
    const int b    = blk >> 1;                    // row (block-uniform)
    const int half = blk & 1;                     // 0 = real half, 1 = imag half
    const int j4b  = half * S4;                   // row-local float4 offset

    // Per-row input sum: one 8B load, L2-resident, block-uniform value.
    const float2 in2 = __ldg(reinterpret_cast<const float2*>(inputs) + b);
    const float  u   = in2.x + in2.y;

    // Uniform param-half selection (no divergence).
    const float4* ap = reinterpret_cast<const float4*>(half ? as_imag : as_real);
    const float4* cp = reinterpret_cast<const float4*>(half ? bs_imag : bs_real);

    const int base = b * NU4 + j4b + threadIdx.x; // global float4 idx, item 0
    const int pj   = threadIdx.x;                 // param idx within half, item 0

    // Front-batch all 4 DRAM-latency state loads (streaming, evict-first).
    float4 s0 = __ldcs(state4 + base + 0 * THREADS);
    float4 s1 = __ldcs(state4 + base + 1 * THREADS);
    float4 s2 = __ldcs(state4 + base + 2 * THREADS);
    float4 s3 = __ldcs(state4 + base + 3 * THREADS);

    // Per-item: param loads are L1/L2-hot (96KB total across grid); compute
    // and store as each state vector's latency is covered by the others.
    #pragma unroll
    for (int k = 0; k < ITEMS; k++) {
        float4 s = (k == 0) ? s0 : (k == 1) ? s1 : (k == 2) ? s2 : s3;
        float4 a = __ldg(ap + pj + k * THREADS);
        float4 c = __ldg(cp + pj + k * THREADS);
        float4 r;
        r.x = fmaf(s.x, a.x, u * c.x);
        r.y = fmaf(s.y, a.y, u * c.y);
        r.z = fmaf(s.z, a.z, u * c.z);
        r.w = fmaf(s.w, a.w, u * c.w);
        const int idx = base + k * THREADS;
        __stcs(out4 + idx, r);
        if (DUP) __stcs(out4 + idx + TOTAL4, r);
    }
}

extern "C" void kernel_launch(void* const* d_in, const int* in_sizes, int n_in,
                              void* d_out, int out_size) {
    const float* inputs  = (const float*)d_in[0];
    const float* state   = (const float*)d_in[1];
    const float* as_real = (const float*)d_in[2];
    const float* as_imag = (const float*)d_in[3];
    const float* bs_real = (const float*)d_in[4];
    const float* bs_imag = (const float*)d_in[5];
    float* out = (float*)d_out;

    const long long total = (long long)BATCH * NUM_UNITS;
    if ((long long)out_size >= 2 * total) {
        lru_cell_kernel<1><<<GRID, THREADS>>>(inputs, state, as_real, as_imag,
                                              bs_real, bs_imag, out);
    } else {
        lru_cell_kernel<0><<<GRID, THREADS>>>(inputs, state, as_real, as_imag,
                                              bs_real, bs_imag, out);
    }
}